// round 6
// baseline (speedup 1.0000x reference)
#include <cuda_runtime.h>

// Problem constants (fixed by the dataset)
#define MAXN 50000
#define MAXE 800000

// Persistent device scratch (allocation-free rule: __device__ globals)
static __device__ __align__(16) float g_sup[MAXN * 32];     // s_up   [n][c]
static __device__ __align__(16) float g_vup[MAXN * 96];     // v_up   [n][x][c]
static __device__ __align__(16) float g_skip_s[MAXN * 64];  // skip_s [n][d]
static __device__ __align__(16) float g_skip_v[MAXN * 96];  // skip_v [n][x][c]
static __device__ __align__(16) float g_agg[MAXN * 256];    // [n][slot][c]

// CSR-by-receiver + permuted edge payload (SoA)
static __device__ int g_cnt[MAXN];
static __device__ int g_off[MAXN];                 // exclusive offsets; after reorder: g_off[n] = end of node n
static __device__ int g_psnd[MAXE];
static __device__ __align__(16) float4 g_psh[MAXE];       // edge_features, permuted
static __device__ __align__(16) float4 g_prad[MAXE * 2];  // radial (8 floats), permuted

__device__ __forceinline__ float silu_f(float x) {
    return x / (1.0f + __expf(-x));
}

// ---------------------------------------------------------------------------
// Kernel A: per-node up-projection + species skip. Also zeroes g_cnt.
// ---------------------------------------------------------------------------
__global__ void node_up_kernel(const float* __restrict__ nf,
                               const int*   __restrict__ species,
                               const float* __restrict__ Wus,   // (32,32)
                               const float* __restrict__ Wuv,   // (32,32)
                               const float* __restrict__ Wss,   // (5,32,64)
                               const float* __restrict__ Wsv,   // (5,32,32)
                               int N)
{
    int warp = (blockIdx.x * blockDim.x + threadIdx.x) >> 5;
    int lane = threadIdx.x & 31;
    if (warp >= N) return;
    int n = warp;

    if (lane == 0) g_cnt[n] = 0;

    const float* nfp = nf + (size_t)n * 128;
    float s  = nfp[lane];
    float v0 = nfp[32 + lane * 3 + 0];
    float v1 = nfp[32 + lane * 3 + 1];
    float v2 = nfp[32 + lane * 3 + 2];
    int sp = species[n];
    const float* wss = Wss + sp * 2048;
    const float* wsv = Wsv + sp * 1024;

    float sup = 0.f, vu0 = 0.f, vu1 = 0.f, vu2 = 0.f;
    float ss0 = 0.f, ss1 = 0.f, sv0 = 0.f, sv1 = 0.f, sv2 = 0.f;

    #pragma unroll
    for (int c = 0; c < 32; ++c) {
        float sb = __shfl_sync(0xffffffffu, s,  c);
        float b0 = __shfl_sync(0xffffffffu, v0, c);
        float b1 = __shfl_sync(0xffffffffu, v1, c);
        float b2 = __shfl_sync(0xffffffffu, v2, c);
        sup = fmaf(sb, __ldg(Wus + c * 32 + lane), sup);
        float wu = __ldg(Wuv + c * 32 + lane);
        vu0 = fmaf(b0, wu, vu0);
        vu1 = fmaf(b1, wu, vu1);
        vu2 = fmaf(b2, wu, vu2);
        ss0 = fmaf(sb, __ldg(wss + c * 64 + lane), ss0);
        ss1 = fmaf(sb, __ldg(wss + c * 64 + 32 + lane), ss1);
        float wv = __ldg(wsv + c * 32 + lane);
        sv0 = fmaf(b0, wv, sv0);
        sv1 = fmaf(b1, wv, sv1);
        sv2 = fmaf(b2, wv, sv2);
    }

    const float isc = 0.17677669529663687f; // 1/sqrt(32)
    g_sup[n * 32 + lane]             = sup * isc;
    g_vup[n * 96 + 0 * 32 + lane]    = vu0 * isc;
    g_vup[n * 96 + 1 * 32 + lane]    = vu1 * isc;
    g_vup[n * 96 + 2 * 32 + lane]    = vu2 * isc;
    g_skip_s[n * 64 + lane]          = ss0 * isc;
    g_skip_s[n * 64 + 32 + lane]     = ss1 * isc;
    g_skip_v[n * 96 + 0 * 32 + lane] = sv0 * isc;
    g_skip_v[n * 96 + 1 * 32 + lane] = sv1 * isc;
    g_skip_v[n * 96 + 2 * 32 + lane] = sv2 * isc;
}

// ---------------------------------------------------------------------------
// CSR build: histogram -> single-block scan -> payload permute
// ---------------------------------------------------------------------------
__global__ void hist_kernel(const int* __restrict__ rcv, int E)
{
    int e = blockIdx.x * blockDim.x + threadIdx.x;
    if (e < E) atomicAdd(&g_cnt[__ldg(rcv + e)], 1);
}

// Single block, 1024 threads; each thread scans a contiguous chunk.
__global__ void scan_kernel(int N)
{
    __shared__ int wsum[32];
    int t = threadIdx.x;
    int lane = t & 31, wid = t >> 5;
    const int CH = (N + 1023) / 1024;
    int st = t * CH;
    int en = st + CH; if (en > N) en = N;

    int s = 0;
    for (int i = st; i < en; ++i) s += g_cnt[i];

    int x = s;
    #pragma unroll
    for (int o = 1; o < 32; o <<= 1) {
        int y = __shfl_up_sync(0xffffffffu, x, o);
        if (lane >= o) x += y;
    }
    if (lane == 31) wsum[wid] = x;
    __syncthreads();
    if (wid == 0) {
        int w = wsum[lane];
        #pragma unroll
        for (int o = 1; o < 32; o <<= 1) {
            int y = __shfl_up_sync(0xffffffffu, w, o);
            if (lane >= o) w += y;
        }
        wsum[lane] = w;
    }
    __syncthreads();

    int run = x - s + (wid ? wsum[wid - 1] : 0);  // exclusive prefix for this thread
    for (int i = st; i < en; ++i) {
        g_off[i] = run;
        run += g_cnt[i];
    }
}

// Permute payload into receiver-sorted SoA; atomicAdd turns g_off[n] into
// the END offset of node n (start of node n = g_off[n-1] afterwards).
__global__ void reorder_kernel(const int* __restrict__ rcv,
                               const int* __restrict__ snd,
                               const float* __restrict__ ef,
                               const float* __restrict__ radial,
                               int E)
{
    int e = blockIdx.x * blockDim.x + threadIdx.x;
    if (e >= E) return;
    int pos = atomicAdd(&g_off[__ldg(rcv + e)], 1);
    g_psnd[pos] = __ldg(snd + e);
    g_psh[pos]  = __ldg((const float4*)(ef + (size_t)e * 4));
    g_prad[pos * 2 + 0] = __ldg((const float4*)(radial + (size_t)e * 8));
    g_prad[pos * 2 + 1] = __ldg((const float4*)(radial + (size_t)e * 8 + 4));
}

// ---------------------------------------------------------------------------
// Kernel B: gather aggregation. Warp per receiver node; 8-edge batches with
// the round-5 verified branch-free body; REGISTER accumulation (no atomics);
// g_agg written once with plain stores.
// Lane math (verified rounds 1/4/5):
//   producer lane P computes w[path=P>>3][4*(P&7)..+3]
//   consumer lane L owns quad qA = slot(L>>4), chans 4*(L&15);  qB = slot+2
// ---------------------------------------------------------------------------
__global__ void __launch_bounds__(256) agg_kernel(
    const float* __restrict__ Wr1,   // (8,8)
    const float* __restrict__ Wr2,   // (8,128)
    int N)
{
    int warp = (blockIdx.x * blockDim.x + threadIdx.x) >> 5;
    int lane = threadIdx.x & 31;
    if (warp >= N) return;
    int n = warp;

    const float inv_sqrt8 = 0.35355339059327373f;
    const float inv_sqrt3 = 0.5773502691896258f;
    const float wk        = 0.08838834764831845f; // inv_sqrt8 * 1/sqrt(16)

    int grp  = lane >> 3;
    int srcA = (grp == 0) ? lane : ((grp == 1) ? lane + 16 : lane - 8);
    int srcB = (grp < 2)  ? lane + 8 : srcA;
    int cidx = (lane & 7) * 4;
    int jj   = lane & 7;

    bool g0 = (grp == 0), g1 = (grp == 1), g2 = (grp == 2);
    bool scalA = ((grp & 1) == 0);

    float wr1r[8];
    #pragma unroll
    for (int i = 0; i < 8; ++i) wr1r[i] = __ldg(Wr1 + i * 8 + jj);
    float4 wr2r[8];
    #pragma unroll
    for (int q = 0; q < 8; ++q) wr2r[q] = __ldg((const float4*)(Wr2 + q * 128 + lane * 4));

    int beg = (n > 0) ? g_off[n - 1] : 0;
    int end = g_off[n];

    float aA0 = 0.f, aA1 = 0.f, aA2 = 0.f, aA3 = 0.f;
    float aB0 = 0.f, aB1 = 0.f, aB2 = 0.f, aB3 = 0.f;

    for (int base = beg; base < end; base += 8) {
        // Batch-load 8 edges' senders (lanes 0-7; clamped within node range)
        int eic = base + jj; if (eic > end - 1) eic = end - 1;
        int snd8 = __ldg(g_psnd + eic);

        // Batch-load 8 edges' radial from permuted array (coalesced float2)
        long rbase = (long)base * 4 + lane;
        long rmax  = (long)end * 4 - 1;
        if (rbase > rmax) rbase = rmax;
        float2 rv = __ldg((const float2*)g_prad + rbase);
        float rvx = rv.x, rvy = rv.y;

        // Batched hidden activations: lane holds h[edge=lane>>3][hid=lane&7]
        // in h0 (edges 0-3) and h1 (edges 4-7).
        float h0, h1;
        {
            int eb = (lane >> 3) * 4;
            float t0 = 0.f, t1 = 0.f;
            #pragma unroll
            for (int i = 0; i < 8; ++i) {
                int sl = eb + (i >> 1);
                float r0 = (i & 1) ? __shfl_sync(0xffffffffu, rvy, sl)
                                   : __shfl_sync(0xffffffffu, rvx, sl);
                float r1 = (i & 1) ? __shfl_sync(0xffffffffu, rvy, sl + 16)
                                   : __shfl_sync(0xffffffffu, rvx, sl + 16);
                t0 = fmaf(r0, wr1r[i], t0);
                t1 = fmaf(r1, wr1r[i], t1);
            }
            h0 = silu_f(t0 * inv_sqrt8);
            h1 = silu_f(t1 * inv_sqrt8);
        }

        #pragma unroll
        for (int j = 0; j < 8; ++j) {
            if (base + j >= end) break;   // uniform across warp
            int snd = __shfl_sync(0xffffffffu, snd8, j);

            float w0 = 0.f, w1 = 0.f, w2 = 0.f, w3 = 0.f;
            #pragma unroll
            for (int q = 0; q < 8; ++q) {
                float hq = (j < 4) ? __shfl_sync(0xffffffffu, h0, (j & 3) * 8 + q)
                                   : __shfl_sync(0xffffffffu, h1, (j & 3) * 8 + q);
                w0 = fmaf(hq, wr2r[q].x, w0);
                w1 = fmaf(hq, wr2r[q].y, w1);
                w2 = fmaf(hq, wr2r[q].z, w2);
                w3 = fmaf(hq, wr2r[q].w, w3);
            }
            w0 *= wk; w1 *= wk; w2 *= wk; w3 *= wk;

            float wA0 = __shfl_sync(0xffffffffu, w0, srcA);
            float wA1 = __shfl_sync(0xffffffffu, w1, srcA);
            float wA2 = __shfl_sync(0xffffffffu, w2, srcA);
            float wA3 = __shfl_sync(0xffffffffu, w3, srcA);
            float wB0 = __shfl_sync(0xffffffffu, w0, srcB);
            float wB1 = __shfl_sync(0xffffffffu, w1, srcB);
            float wB2 = __shfl_sync(0xffffffffu, w2, srcB);
            float wB3 = __shfl_sync(0xffffffffu, w3, srcB);

            float4 sh = __ldg(g_psh + (base + j));   // broadcast, sequential

            const float* vb = g_vup + (size_t)snd * 96 + cidx;
            float4 se  = __ldg((const float4*)(g_sup + (size_t)snd * 32 + cidx));
            float4 ve0 = __ldg((const float4*)(vb));
            float4 ve1 = __ldg((const float4*)(vb + 32));
            float4 ve2 = __ldg((const float4*)(vb + 64));

            float d0 = fmaf(ve2.x, sh.w, fmaf(ve1.x, sh.z, ve0.x * sh.y));
            float d1 = fmaf(ve2.y, sh.w, fmaf(ve1.y, sh.z, ve0.y * sh.y));
            float d2 = fmaf(ve2.z, sh.w, fmaf(ve1.z, sh.z, ve0.z * sh.y));
            float d3 = fmaf(ve2.w, sh.w, fmaf(ve1.w, sh.z, ve0.w * sh.y));

            float sA = g1 ? inv_sqrt3 : (g2 ? sh.y : sh.x);
            float sB = g0 ? sh.z : (g2 ? sh.w : sh.x);

            float bA0 = scalA ? se.x : (g1 ? d0 : ve0.x);
            float bA1 = scalA ? se.y : (g1 ? d1 : ve0.y);
            float bA2 = scalA ? se.z : (g1 ? d2 : ve0.z);
            float bA3 = scalA ? se.w : (g1 ? d3 : ve0.w);

            float bB0 = scalA ? se.x : (g1 ? ve1.x : ve2.x);
            float bB1 = scalA ? se.y : (g1 ? ve1.y : ve2.y);
            float bB2 = scalA ? se.z : (g1 ? ve1.z : ve2.z);
            float bB3 = scalA ? se.w : (g1 ? ve1.w : ve2.w);

            aA0 = fmaf(wA0 * sA, bA0, aA0);
            aA1 = fmaf(wA1 * sA, bA1, aA1);
            aA2 = fmaf(wA2 * sA, bA2, aA2);
            aA3 = fmaf(wA3 * sA, bA3, aA3);
            aB0 = fmaf(wB0 * sB, bB0, aB0);
            aB1 = fmaf(wB1 * sB, bB1, aB1);
            aB2 = fmaf(wB2 * sB, bB2, aB2);
            aB3 = fmaf(wB3 * sB, bB3, aB3);
        }
    }

    float* dst = g_agg + (size_t)n * 256 + (lane >> 4) * 64 + (lane & 15) * 4;
    *(float4*)dst         = make_float4(aA0, aA1, aA2, aA3);
    *(float4*)(dst + 128) = make_float4(aB0, aB1, aB2, aB3);
}

// ---------------------------------------------------------------------------
// Kernel C: per-node down-projection + skip average + gated output (UNCHANGED).
// ---------------------------------------------------------------------------
__global__ void node_down_kernel(const float* __restrict__ Wds,  // (64,64)
                                 const float* __restrict__ Wdv,  // (64,32)
                                 float* __restrict__ out,
                                 int N)
{
    int warp = (blockIdx.x * blockDim.x + threadIdx.x) >> 5;
    int lane = threadIdx.x & 31;
    if (warp >= N) return;
    int n = warp;

    const float* ag = g_agg + (size_t)n * 256;
    float a0l  = ag[lane],        a0h  = ag[32 + lane];
    float a1l0 = ag[64 + lane],   a1h0 = ag[96 + lane];
    float a1l1 = ag[128 + lane],  a1h1 = ag[160 + lane];
    float a1l2 = ag[192 + lane],  a1h2 = ag[224 + lane];

    float sc0 = 0.f, sc1 = 0.f, vc0 = 0.f, vc1 = 0.f, vc2 = 0.f;

    #pragma unroll
    for (int c = 0; c < 32; ++c) {
        float b0 = __shfl_sync(0xffffffffu, a0l, c);
        float b1 = __shfl_sync(0xffffffffu, a0h, c);
        sc0 = fmaf(b0, __ldg(Wds + c * 64 + lane), sc0);
        sc0 = fmaf(b1, __ldg(Wds + (32 + c) * 64 + lane), sc0);
        sc1 = fmaf(b0, __ldg(Wds + c * 64 + 32 + lane), sc1);
        sc1 = fmaf(b1, __ldg(Wds + (32 + c) * 64 + 32 + lane), sc1);
        float wv0 = __ldg(Wdv + c * 32 + lane);
        float wv1 = __ldg(Wdv + (32 + c) * 32 + lane);
        vc0 = fmaf(__shfl_sync(0xffffffffu, a1l0, c), wv0, vc0);
        vc0 = fmaf(__shfl_sync(0xffffffffu, a1h0, c), wv1, vc0);
        vc1 = fmaf(__shfl_sync(0xffffffffu, a1l1, c), wv0, vc1);
        vc1 = fmaf(__shfl_sync(0xffffffffu, a1h1, c), wv1, vc1);
        vc2 = fmaf(__shfl_sync(0xffffffffu, a1l2, c), wv0, vc2);
        vc2 = fmaf(__shfl_sync(0xffffffffu, a1h2, c), wv1, vc2);
    }

    const float i2c = 0.125f; // 1/sqrt(64)
    float scl = 0.5f * (sc0 * i2c + g_skip_s[n * 64 + lane]);
    float sch = 0.5f * (sc1 * i2c + g_skip_s[n * 64 + 32 + lane]);
    float feat = silu_f(scl);
    float gate = silu_f(sch);

    float vg0 = 0.5f * (vc0 * i2c + g_skip_v[n * 96 +      lane]) * gate;
    float vg1 = 0.5f * (vc1 * i2c + g_skip_v[n * 96 + 32 + lane]) * gate;
    float vg2 = 0.5f * (vc2 * i2c + g_skip_v[n * 96 + 64 + lane]) * gate;

    float* o = out + (size_t)n * 128;
    o[lane] = feat;
    o[32 + 3 * lane + 0] = vg0;
    o[32 + 3 * lane + 1] = vg1;
    o[32 + 3 * lane + 2] = vg2;
}

// ---------------------------------------------------------------------------
extern "C" void kernel_launch(void* const* d_in, const int* in_sizes, int n_in,
                              void* d_out, int out_size)
{
    const float* nf      = (const float*)d_in[0];
    const float* ef      = (const float*)d_in[1];
    const float* radial  = (const float*)d_in[2];
    const int*   snd     = (const int*)  d_in[3];
    const int*   rcv     = (const int*)  d_in[4];
    const int*   species = (const int*)  d_in[5];
    const float* Wus     = (const float*)d_in[6];
    const float* Wuv     = (const float*)d_in[7];
    const float* Wr1     = (const float*)d_in[8];
    const float* Wr2     = (const float*)d_in[9];
    const float* Wds     = (const float*)d_in[10];
    const float* Wdv     = (const float*)d_in[11];
    const float* Wss     = (const float*)d_in[12];
    const float* Wsv     = (const float*)d_in[13];
    float* out = (float*)d_out;

    int N = in_sizes[0] / 128;
    int E = in_sizes[3];

    node_up_kernel  <<<(N + 7) / 8, 256>>>(nf, species, Wus, Wuv, Wss, Wsv, N);
    hist_kernel     <<<(E + 255) / 256, 256>>>(rcv, E);
    scan_kernel     <<<1, 1024>>>(N);
    reorder_kernel  <<<(E + 255) / 256, 256>>>(rcv, snd, ef, radial, E);
    agg_kernel      <<<(N + 7) / 8, 256>>>(Wr1, Wr2, N);
    node_down_kernel<<<(N + 7) / 8, 256>>>(Wds, Wdv, out, N);
}

// round 7
// speedup vs baseline: 1.1243x; 1.1243x over previous
#include <cuda_runtime.h>

// Problem constants (fixed by the dataset)
#define MAXN 50000
#define MAXE 800000

// Persistent device scratch (allocation-free rule: __device__ globals)
static __device__ __align__(16) float g_sup[MAXN * 32];     // s_up   [n][c]
static __device__ __align__(16) float g_vup[MAXN * 96];     // v_up   [n][x][c]
static __device__ __align__(16) float g_skip_s[MAXN * 64];  // skip_s [n][d]
static __device__ __align__(16) float g_skip_v[MAXN * 96];  // skip_v [n][x][c]
static __device__ __align__(16) float g_agg[MAXN * 256];    // [n][slot][c]

// CSR-by-receiver + permuted edge payload (SoA)
static __device__ int g_cnt[MAXN];
static __device__ int g_off[MAXN];                 // exclusive offsets; mutated by reorder
static __device__ int g_psnd[MAXE];
static __device__ int g_prcv[MAXE];
static __device__ __align__(16) float4 g_psh[MAXE];       // edge_features, permuted
static __device__ __align__(16) float4 g_prad[MAXE * 2];  // radial (8 floats), permuted

__device__ __forceinline__ float silu_f(float x) {
    return x / (1.0f + __expf(-x));
}

__device__ __forceinline__ void red_add_v4(float* p, float a, float b, float c, float d) {
    asm volatile("red.global.add.v4.f32 [%0], {%1,%2,%3,%4};"
                 :: "l"(p), "f"(a), "f"(b), "f"(c), "f"(d)
                 : "memory");
}

// ---------------------------------------------------------------------------
// Kernel A: per-node up-projection + species skip (UNCHANGED math).
// Also zeroes g_cnt and this node's agg slab.
// ---------------------------------------------------------------------------
__global__ void node_up_kernel(const float* __restrict__ nf,
                               const int*   __restrict__ species,
                               const float* __restrict__ Wus,   // (32,32)
                               const float* __restrict__ Wuv,   // (32,32)
                               const float* __restrict__ Wss,   // (5,32,64)
                               const float* __restrict__ Wsv,   // (5,32,32)
                               int N)
{
    int warp = (blockIdx.x * blockDim.x + threadIdx.x) >> 5;
    int lane = threadIdx.x & 31;
    if (warp >= N) return;
    int n = warp;

    if (lane == 0) g_cnt[n] = 0;

    const float* nfp = nf + (size_t)n * 128;
    float s  = nfp[lane];
    float v0 = nfp[32 + lane * 3 + 0];
    float v1 = nfp[32 + lane * 3 + 1];
    float v2 = nfp[32 + lane * 3 + 2];
    int sp = species[n];
    const float* wss = Wss + sp * 2048;
    const float* wsv = Wsv + sp * 1024;

    float sup = 0.f, vu0 = 0.f, vu1 = 0.f, vu2 = 0.f;
    float ss0 = 0.f, ss1 = 0.f, sv0 = 0.f, sv1 = 0.f, sv2 = 0.f;

    #pragma unroll
    for (int c = 0; c < 32; ++c) {
        float sb = __shfl_sync(0xffffffffu, s,  c);
        float b0 = __shfl_sync(0xffffffffu, v0, c);
        float b1 = __shfl_sync(0xffffffffu, v1, c);
        float b2 = __shfl_sync(0xffffffffu, v2, c);
        sup = fmaf(sb, __ldg(Wus + c * 32 + lane), sup);
        float wu = __ldg(Wuv + c * 32 + lane);
        vu0 = fmaf(b0, wu, vu0);
        vu1 = fmaf(b1, wu, vu1);
        vu2 = fmaf(b2, wu, vu2);
        ss0 = fmaf(sb, __ldg(wss + c * 64 + lane), ss0);
        ss1 = fmaf(sb, __ldg(wss + c * 64 + 32 + lane), ss1);
        float wv = __ldg(wsv + c * 32 + lane);
        sv0 = fmaf(b0, wv, sv0);
        sv1 = fmaf(b1, wv, sv1);
        sv2 = fmaf(b2, wv, sv2);
    }

    const float isc = 0.17677669529663687f; // 1/sqrt(32)
    g_sup[n * 32 + lane]             = sup * isc;
    g_vup[n * 96 + 0 * 32 + lane]    = vu0 * isc;
    g_vup[n * 96 + 1 * 32 + lane]    = vu1 * isc;
    g_vup[n * 96 + 2 * 32 + lane]    = vu2 * isc;
    g_skip_s[n * 64 + lane]          = ss0 * isc;
    g_skip_s[n * 64 + 32 + lane]     = ss1 * isc;
    g_skip_v[n * 96 + 0 * 32 + lane] = sv0 * isc;
    g_skip_v[n * 96 + 1 * 32 + lane] = sv1 * isc;
    g_skip_v[n * 96 + 2 * 32 + lane] = sv2 * isc;

    #pragma unroll
    for (int k = 0; k < 2; ++k)
        *(float4*)(g_agg + n * 256 + (k * 32 + lane) * 4) = make_float4(0.f, 0.f, 0.f, 0.f);
}

// ---------------------------------------------------------------------------
// CSR build: histogram -> single-block scan -> payload permute
// ---------------------------------------------------------------------------
__global__ void hist_kernel(const int* __restrict__ rcv, int E)
{
    int e = blockIdx.x * blockDim.x + threadIdx.x;
    if (e < E) atomicAdd(&g_cnt[__ldg(rcv + e)], 1);
}

__global__ void scan_kernel(int N)
{
    __shared__ int wsum[32];
    int t = threadIdx.x;
    int lane = t & 31, wid = t >> 5;
    const int CH = (N + 1023) / 1024;
    int st = t * CH;
    int en = st + CH; if (en > N) en = N;

    int s = 0;
    for (int i = st; i < en; ++i) s += g_cnt[i];

    int x = s;
    #pragma unroll
    for (int o = 1; o < 32; o <<= 1) {
        int y = __shfl_up_sync(0xffffffffu, x, o);
        if (lane >= o) x += y;
    }
    if (lane == 31) wsum[wid] = x;
    __syncthreads();
    if (wid == 0) {
        int w = wsum[lane];
        #pragma unroll
        for (int o = 1; o < 32; o <<= 1) {
            int y = __shfl_up_sync(0xffffffffu, w, o);
            if (lane >= o) w += y;
        }
        wsum[lane] = w;
    }
    __syncthreads();

    int run = x - s + (wid ? wsum[wid - 1] : 0);
    for (int i = st; i < en; ++i) {
        g_off[i] = run;
        run += g_cnt[i];
    }
}

// Permute payload (incl. receiver) into receiver-sorted SoA arrays.
__global__ void reorder_kernel(const int* __restrict__ rcv,
                               const int* __restrict__ snd,
                               const float* __restrict__ ef,
                               const float* __restrict__ radial,
                               int E)
{
    int e = blockIdx.x * blockDim.x + threadIdx.x;
    if (e >= E) return;
    int r = __ldg(rcv + e);
    int pos = atomicAdd(&g_off[r], 1);
    g_prcv[pos] = r;
    g_psnd[pos] = __ldg(snd + e);
    g_psh[pos]  = __ldg((const float4*)(ef + (size_t)e * 4));
    g_prad[pos * 2 + 0] = __ldg((const float4*)(radial + (size_t)e * 8));
    g_prad[pos * 2 + 1] = __ldg((const float4*)(radial + (size_t)e * 8 + 4));
}

// ---------------------------------------------------------------------------
// Kernel B: SORTED scatter edge kernel, 8 edges per warp, branch-free body
// (round-5 verified), + warp-local run combining: contributions to the same
// receiver (adjacent after sort, mean run 16) accumulate in registers and
// flush with red.v4 only at run boundaries -> ~5x fewer REDG ops.
// Lane math (verified rounds 1/4/5):
//   producer lane P computes w[path=P>>3][4*(P&7)..+3]
//   consumer lane L owns quad qA = slot(L>>4), chans 4*(L&15);  qB = slot+2
// ---------------------------------------------------------------------------
__global__ void __launch_bounds__(256) edge_kernel(
    const float* __restrict__ Wr1,   // (8,8)
    const float* __restrict__ Wr2,   // (8,128)
    int E)
{
    int warp = (blockIdx.x * blockDim.x + threadIdx.x) >> 5;
    int lane = threadIdx.x & 31;
    int base = warp * 8;
    if (base >= E) return;

    const float inv_sqrt8 = 0.35355339059327373f;
    const float inv_sqrt3 = 0.5773502691896258f;
    const float wk        = 0.08838834764831845f; // inv_sqrt8 * 1/sqrt(16)

    int grp  = lane >> 3;
    int srcA = (grp == 0) ? lane : ((grp == 1) ? lane + 16 : lane - 8);
    int srcB = (grp < 2)  ? lane + 8 : srcA;
    int cidx = (lane & 7) * 4;
    int jj   = lane & 7;
    int loff = (lane >> 4) * 64 + (lane & 15) * 4;

    bool g0 = (grp == 0), g1 = (grp == 1), g2 = (grp == 2);
    bool scalA = ((grp & 1) == 0);

    float wr1r[8];
    #pragma unroll
    for (int i = 0; i < 8; ++i) wr1r[i] = __ldg(Wr1 + i * 8 + jj);
    float4 wr2r[8];
    #pragma unroll
    for (int q = 0; q < 8; ++q) wr2r[q] = __ldg((const float4*)(Wr2 + q * 128 + lane * 4));

    // Batch-load 8 edges' sender+receiver (lanes 0-7; clamped for tail)
    int eic = base + jj; if (eic > E - 1) eic = E - 1;
    int snd8 = __ldg(g_psnd + eic);
    int rcv8 = __ldg(g_prcv + eic);

    // Batch-load 8 edges' radial (coalesced float2 from permuted array)
    long rbase = (long)base * 4 + lane;
    long rmax  = (long)E * 4 - 1;
    if (rbase > rmax) rbase = rmax;
    float2 rv = __ldg((const float2*)g_prad + rbase);
    float rvx = rv.x, rvy = rv.y;

    // Batched hidden activations: lane holds h[edge=lane>>3][hid=lane&7]
    // in h0 (edges 0-3) and h1 (edges 4-7).
    float h0, h1;
    {
        int eb = (lane >> 3) * 4;
        float t0 = 0.f, t1 = 0.f;
        #pragma unroll
        for (int i = 0; i < 8; ++i) {
            int sl = eb + (i >> 1);
            float r0 = (i & 1) ? __shfl_sync(0xffffffffu, rvy, sl)
                               : __shfl_sync(0xffffffffu, rvx, sl);
            float r1 = (i & 1) ? __shfl_sync(0xffffffffu, rvy, sl + 16)
                               : __shfl_sync(0xffffffffu, rvx, sl + 16);
            t0 = fmaf(r0, wr1r[i], t0);
            t1 = fmaf(r1, wr1r[i], t1);
        }
        h0 = silu_f(t0 * inv_sqrt8);
        h1 = silu_f(t1 * inv_sqrt8);
    }

    // Run-combining accumulators
    float aA0 = 0.f, aA1 = 0.f, aA2 = 0.f, aA3 = 0.f;
    float aB0 = 0.f, aB1 = 0.f, aB2 = 0.f, aB3 = 0.f;
    int curr = __shfl_sync(0xffffffffu, rcv8, 0);   // warp-uniform

    #pragma unroll
    for (int j = 0; j < 8; ++j) {
        bool vj = (base + j) < E;
        int snd  = __shfl_sync(0xffffffffu, snd8, j);
        int rcvj = __shfl_sync(0xffffffffu, rcv8, j);

        // flush on receiver change (warp-uniform branch)
        if (rcvj != curr) {
            float* dst = g_agg + (size_t)curr * 256 + loff;
            red_add_v4(dst,       aA0, aA1, aA2, aA3);
            red_add_v4(dst + 128, aB0, aB1, aB2, aB3);
            aA0 = aA1 = aA2 = aA3 = 0.f;
            aB0 = aB1 = aB2 = aB3 = 0.f;
            curr = rcvj;
        }

        float w0 = 0.f, w1 = 0.f, w2 = 0.f, w3 = 0.f;
        #pragma unroll
        for (int q = 0; q < 8; ++q) {
            float hq = (j < 4) ? __shfl_sync(0xffffffffu, h0, (j & 3) * 8 + q)
                               : __shfl_sync(0xffffffffu, h1, (j & 3) * 8 + q);
            w0 = fmaf(hq, wr2r[q].x, w0);
            w1 = fmaf(hq, wr2r[q].y, w1);
            w2 = fmaf(hq, wr2r[q].z, w2);
            w3 = fmaf(hq, wr2r[q].w, w3);
        }
        w0 *= wk; w1 *= wk; w2 *= wk; w3 *= wk;

        float wA0 = __shfl_sync(0xffffffffu, w0, srcA);
        float wA1 = __shfl_sync(0xffffffffu, w1, srcA);
        float wA2 = __shfl_sync(0xffffffffu, w2, srcA);
        float wA3 = __shfl_sync(0xffffffffu, w3, srcA);
        float wB0 = __shfl_sync(0xffffffffu, w0, srcB);
        float wB1 = __shfl_sync(0xffffffffu, w1, srcB);
        float wB2 = __shfl_sync(0xffffffffu, w2, srcB);
        float wB3 = __shfl_sync(0xffffffffu, w3, srcB);

        int ee = vj ? (base + j) : (E - 1);
        float4 sh = __ldg(g_psh + ee);   // broadcast, sequential

        const float* vb = g_vup + (size_t)snd * 96 + cidx;
        float4 se  = __ldg((const float4*)(g_sup + (size_t)snd * 32 + cidx));
        float4 ve0 = __ldg((const float4*)(vb));
        float4 ve1 = __ldg((const float4*)(vb + 32));
        float4 ve2 = __ldg((const float4*)(vb + 64));

        float d0 = fmaf(ve2.x, sh.w, fmaf(ve1.x, sh.z, ve0.x * sh.y));
        float d1 = fmaf(ve2.y, sh.w, fmaf(ve1.y, sh.z, ve0.y * sh.y));
        float d2 = fmaf(ve2.z, sh.w, fmaf(ve1.z, sh.z, ve0.z * sh.y));
        float d3 = fmaf(ve2.w, sh.w, fmaf(ve1.w, sh.z, ve0.w * sh.y));

        float sA = g1 ? inv_sqrt3 : (g2 ? sh.y : sh.x);
        float sB = g0 ? sh.z : (g2 ? sh.w : sh.x);
        sA = vj ? sA : 0.f;              // tail edges contribute zero
        sB = vj ? sB : 0.f;

        float bA0 = scalA ? se.x : (g1 ? d0 : ve0.x);
        float bA1 = scalA ? se.y : (g1 ? d1 : ve0.y);
        float bA2 = scalA ? se.z : (g1 ? d2 : ve0.z);
        float bA3 = scalA ? se.w : (g1 ? d3 : ve0.w);

        float bB0 = scalA ? se.x : (g1 ? ve1.x : ve2.x);
        float bB1 = scalA ? se.y : (g1 ? ve1.y : ve2.y);
        float bB2 = scalA ? se.z : (g1 ? ve1.z : ve2.z);
        float bB3 = scalA ? se.w : (g1 ? ve1.w : ve2.w);

        aA0 = fmaf(wA0 * sA, bA0, aA0);
        aA1 = fmaf(wA1 * sA, bA1, aA1);
        aA2 = fmaf(wA2 * sA, bA2, aA2);
        aA3 = fmaf(wA3 * sA, bA3, aA3);
        aB0 = fmaf(wB0 * sB, bB0, aB0);
        aB1 = fmaf(wB1 * sB, bB1, aB1);
        aB2 = fmaf(wB2 * sB, bB2, aB2);
        aB3 = fmaf(wB3 * sB, bB3, aB3);
    }

    // final flush
    {
        float* dst = g_agg + (size_t)curr * 256 + loff;
        red_add_v4(dst,       aA0, aA1, aA2, aA3);
        red_add_v4(dst + 128, aB0, aB1, aB2, aB3);
    }
}

// ---------------------------------------------------------------------------
// Kernel C: per-node down-projection + skip average + gated output (UNCHANGED).
// ---------------------------------------------------------------------------
__global__ void node_down_kernel(const float* __restrict__ Wds,  // (64,64)
                                 const float* __restrict__ Wdv,  // (64,32)
                                 float* __restrict__ out,
                                 int N)
{
    int warp = (blockIdx.x * blockDim.x + threadIdx.x) >> 5;
    int lane = threadIdx.x & 31;
    if (warp >= N) return;
    int n = warp;

    const float* ag = g_agg + (size_t)n * 256;
    float a0l  = ag[lane],        a0h  = ag[32 + lane];
    float a1l0 = ag[64 + lane],   a1h0 = ag[96 + lane];
    float a1l1 = ag[128 + lane],  a1h1 = ag[160 + lane];
    float a1l2 = ag[192 + lane],  a1h2 = ag[224 + lane];

    float sc0 = 0.f, sc1 = 0.f, vc0 = 0.f, vc1 = 0.f, vc2 = 0.f;

    #pragma unroll
    for (int c = 0; c < 32; ++c) {
        float b0 = __shfl_sync(0xffffffffu, a0l, c);
        float b1 = __shfl_sync(0xffffffffu, a0h, c);
        sc0 = fmaf(b0, __ldg(Wds + c * 64 + lane), sc0);
        sc0 = fmaf(b1, __ldg(Wds + (32 + c) * 64 + lane), sc0);
        sc1 = fmaf(b0, __ldg(Wds + c * 64 + 32 + lane), sc1);
        sc1 = fmaf(b1, __ldg(Wds + (32 + c) * 64 + 32 + lane), sc1);
        float wv0 = __ldg(Wdv + c * 32 + lane);
        float wv1 = __ldg(Wdv + (32 + c) * 32 + lane);
        vc0 = fmaf(__shfl_sync(0xffffffffu, a1l0, c), wv0, vc0);
        vc0 = fmaf(__shfl_sync(0xffffffffu, a1h0, c), wv1, vc0);
        vc1 = fmaf(__shfl_sync(0xffffffffu, a1l1, c), wv0, vc1);
        vc1 = fmaf(__shfl_sync(0xffffffffu, a1h1, c), wv1, vc1);
        vc2 = fmaf(__shfl_sync(0xffffffffu, a1l2, c), wv0, vc2);
        vc2 = fmaf(__shfl_sync(0xffffffffu, a1h2, c), wv1, vc2);
    }

    const float i2c = 0.125f; // 1/sqrt(64)
    float scl = 0.5f * (sc0 * i2c + g_skip_s[n * 64 + lane]);
    float sch = 0.5f * (sc1 * i2c + g_skip_s[n * 64 + 32 + lane]);
    float feat = silu_f(scl);
    float gate = silu_f(sch);

    float vg0 = 0.5f * (vc0 * i2c + g_skip_v[n * 96 +      lane]) * gate;
    float vg1 = 0.5f * (vc1 * i2c + g_skip_v[n * 96 + 32 + lane]) * gate;
    float vg2 = 0.5f * (vc2 * i2c + g_skip_v[n * 96 + 64 + lane]) * gate;

    float* o = out + (size_t)n * 128;
    o[lane] = feat;
    o[32 + 3 * lane + 0] = vg0;
    o[32 + 3 * lane + 1] = vg1;
    o[32 + 3 * lane + 2] = vg2;
}

// ---------------------------------------------------------------------------
extern "C" void kernel_launch(void* const* d_in, const int* in_sizes, int n_in,
                              void* d_out, int out_size)
{
    const float* nf      = (const float*)d_in[0];
    const float* ef      = (const float*)d_in[1];
    const float* radial  = (const float*)d_in[2];
    const int*   snd     = (const int*)  d_in[3];
    const int*   rcv     = (const int*)  d_in[4];
    const int*   species = (const int*)  d_in[5];
    const float* Wus     = (const float*)d_in[6];
    const float* Wuv     = (const float*)d_in[7];
    const float* Wr1     = (const float*)d_in[8];
    const float* Wr2     = (const float*)d_in[9];
    const float* Wds     = (const float*)d_in[10];
    const float* Wdv     = (const float*)d_in[11];
    const float* Wss     = (const float*)d_in[12];
    const float* Wsv     = (const float*)d_in[13];
    float* out = (float*)d_out;

    int N = in_sizes[0] / 128;
    int E = in_sizes[3];

    int ewarps  = (E + 7) / 8;
    int eblocks = (ewarps + 7) / 8;

    node_up_kernel  <<<(N + 7) / 8, 256>>>(nf, species, Wus, Wuv, Wss, Wsv, N);
    hist_kernel     <<<(E + 255) / 256, 256>>>(rcv, E);
    scan_kernel     <<<1, 1024>>>(N);
    reorder_kernel  <<<(E + 255) / 256, 256>>>(rcv, snd, ef, radial, E);
    edge_kernel     <<<eblocks, 256>>>(Wr1, Wr2, E);
    node_down_kernel<<<(N + 7) / 8, 256>>>(Wds, Wdv, out, N);
}

// round 8
// speedup vs baseline: 1.4440x; 1.2844x over previous
#include <cuda_runtime.h>

// Problem constants (fixed by the dataset)
#define MAXN 50000
#define MAXE 800000

// Persistent device scratch (allocation-free rule: __device__ globals)
static __device__ __align__(16) float g_sup[MAXN * 32];     // s_up   [n][c]
static __device__ __align__(16) float g_vup[MAXN * 96];     // v_up   [n][x][c]
static __device__ __align__(16) float g_skip_s[MAXN * 64];  // skip_s [n][d]
static __device__ __align__(16) float g_skip_v[MAXN * 96];  // skip_v [n][x][c]
static __device__ __align__(16) float g_agg[MAXN * 256];    // [n][slot][c]

__device__ __forceinline__ float silu_f(float x) {
    return x / (1.0f + __expf(-x));
}

__device__ __forceinline__ void red_add_v4(float* p, float a, float b, float c, float d) {
    asm volatile("red.global.add.v4.f32 [%0], {%1,%2,%3,%4};"
                 :: "l"(p), "f"(a), "f"(b), "f"(c), "f"(d)
                 : "memory");
}

// ---------------------------------------------------------------------------
// Kernel A: per-node up-projection + species skip (UNCHANGED, round-1 verified).
// Warp per node; lane = channel. Also zeroes this node's agg slab.
// ---------------------------------------------------------------------------
__global__ void node_up_kernel(const float* __restrict__ nf,
                               const int*   __restrict__ species,
                               const float* __restrict__ Wus,   // (32,32)
                               const float* __restrict__ Wuv,   // (32,32)
                               const float* __restrict__ Wss,   // (5,32,64)
                               const float* __restrict__ Wsv,   // (5,32,32)
                               int N)
{
    int warp = (blockIdx.x * blockDim.x + threadIdx.x) >> 5;
    int lane = threadIdx.x & 31;
    if (warp >= N) return;
    int n = warp;

    const float* nfp = nf + (size_t)n * 128;
    float s  = nfp[lane];
    float v0 = nfp[32 + lane * 3 + 0];
    float v1 = nfp[32 + lane * 3 + 1];
    float v2 = nfp[32 + lane * 3 + 2];
    int sp = species[n];
    const float* wss = Wss + sp * 2048;
    const float* wsv = Wsv + sp * 1024;

    float sup = 0.f, vu0 = 0.f, vu1 = 0.f, vu2 = 0.f;
    float ss0 = 0.f, ss1 = 0.f, sv0 = 0.f, sv1 = 0.f, sv2 = 0.f;

    #pragma unroll
    for (int c = 0; c < 32; ++c) {
        float sb = __shfl_sync(0xffffffffu, s,  c);
        float b0 = __shfl_sync(0xffffffffu, v0, c);
        float b1 = __shfl_sync(0xffffffffu, v1, c);
        float b2 = __shfl_sync(0xffffffffu, v2, c);
        sup = fmaf(sb, __ldg(Wus + c * 32 + lane), sup);
        float wu = __ldg(Wuv + c * 32 + lane);
        vu0 = fmaf(b0, wu, vu0);
        vu1 = fmaf(b1, wu, vu1);
        vu2 = fmaf(b2, wu, vu2);
        ss0 = fmaf(sb, __ldg(wss + c * 64 + lane), ss0);
        ss1 = fmaf(sb, __ldg(wss + c * 64 + 32 + lane), ss1);
        float wv = __ldg(wsv + c * 32 + lane);
        sv0 = fmaf(b0, wv, sv0);
        sv1 = fmaf(b1, wv, sv1);
        sv2 = fmaf(b2, wv, sv2);
    }

    const float isc = 0.17677669529663687f; // 1/sqrt(32)
    g_sup[n * 32 + lane]             = sup * isc;
    g_vup[n * 96 + 0 * 32 + lane]    = vu0 * isc;
    g_vup[n * 96 + 1 * 32 + lane]    = vu1 * isc;
    g_vup[n * 96 + 2 * 32 + lane]    = vu2 * isc;
    g_skip_s[n * 64 + lane]          = ss0 * isc;
    g_skip_s[n * 64 + 32 + lane]     = ss1 * isc;
    g_skip_v[n * 96 + 0 * 32 + lane] = sv0 * isc;
    g_skip_v[n * 96 + 1 * 32 + lane] = sv1 * isc;
    g_skip_v[n * 96 + 2 * 32 + lane] = sv2 * isc;

    #pragma unroll
    for (int k = 0; k < 2; ++k)
        *(float4*)(g_agg + n * 256 + (k * 32 + lane) * 4) = make_float4(0.f, 0.f, 0.f, 0.f);
}

// ---------------------------------------------------------------------------
// Kernel B: edge kernel, 8 edges per warp, branch-free body.
// Round-8 changes vs round 5 (the 352us champion):
//   * __launch_bounds__(256, 3) -> >=24 warps/SM for gather-latency hiding
//   * 3 address-selected gathers instead of 4 uniform ones:
//       q1 = scalA ? se : ve0
//       q2 = g1 ? ve1 : (g3 ? ve2 : se)
//       q3 = g1 ? ve2 : se
//     then bA = g1 ? dot(q1..q3, sh1) : q1 ;  bB = oddgrp ? q2 : q1
//   (verified against the round-1 lane map for all four groups)
// ---------------------------------------------------------------------------
__global__ void __launch_bounds__(256, 3) edge_kernel(
    const float* __restrict__ ef,
    const float* __restrict__ radial,
    const int*   __restrict__ snd_,
    const int*   __restrict__ rcv_,
    const float* __restrict__ Wr1,   // (8,8)
    const float* __restrict__ Wr2,   // (8,128)
    int E)
{
    int warp = (blockIdx.x * blockDim.x + threadIdx.x) >> 5;
    int lane = threadIdx.x & 31;
    int base = warp * 8;
    if (base >= E) return;

    const float inv_sqrt8 = 0.35355339059327373f;
    const float inv_sqrt3 = 0.5773502691896258f;
    const float wk        = 0.08838834764831845f; // inv_sqrt8 * 1/sqrt(16)

    int grp  = lane >> 3;
    int srcA = (grp == 0) ? lane : ((grp == 1) ? lane + 16 : lane - 8);
    int srcB = (grp < 2)  ? lane + 8 : srcA;
    int cidx = (lane & 7) * 4;
    int jj   = lane & 7;
    int loff = (lane >> 4) * 64 + (lane & 15) * 4;

    bool g0 = (grp == 0), g1 = (grp == 1), g2 = (grp == 2), g3 = (grp == 3);
    bool scalA = ((grp & 1) == 0);
    bool oddg  = !scalA;

    float wr1r[8];
    #pragma unroll
    for (int i = 0; i < 8; ++i) wr1r[i] = __ldg(Wr1 + i * 8 + jj);
    float4 wr2r[8];
    #pragma unroll
    for (int q = 0; q < 8; ++q) wr2r[q] = __ldg((const float4*)(Wr2 + q * 128 + lane * 4));

    // Batch-load 8 edges' indices (lanes 0-7; clamped for tail safety)
    int eic = base + jj; if (eic > E - 1) eic = E - 1;
    int snd8 = __ldg(snd_ + eic);
    int rcv8 = __ldg(rcv_ + eic);

    // Batch-load 8 edges' radial (64 floats, coalesced float2 per lane)
    size_t rbase = (size_t)base * 4 + lane;
    size_t rmax  = (size_t)E * 4 - 1;
    if (rbase > rmax) rbase = rmax;
    float2 rv = __ldg((const float2*)radial + rbase);
    float rvx = rv.x, rvy = rv.y;

    // Batched hidden activations: lane holds h[edge=lane>>3][hid=lane&7]
    // in h0 (edges 0-3) and h1 (edges 4-7).
    float h0, h1;
    {
        int eb = (lane >> 3) * 4;
        float t0 = 0.f, t1 = 0.f;
        #pragma unroll
        for (int i = 0; i < 8; ++i) {
            int sl = eb + (i >> 1);
            float r0 = (i & 1) ? __shfl_sync(0xffffffffu, rvy, sl)
                               : __shfl_sync(0xffffffffu, rvx, sl);
            float r1 = (i & 1) ? __shfl_sync(0xffffffffu, rvy, sl + 16)
                               : __shfl_sync(0xffffffffu, rvx, sl + 16);
            t0 = fmaf(r0, wr1r[i], t0);
            t1 = fmaf(r1, wr1r[i], t1);
        }
        h0 = silu_f(t0 * inv_sqrt8);
        h1 = silu_f(t1 * inv_sqrt8);
    }

    #pragma unroll
    for (int j = 0; j < 8; ++j) {
        bool vj = (base + j) < E;
        int snd = __shfl_sync(0xffffffffu, snd8, j);
        int rcv = __shfl_sync(0xffffffffu, rcv8, j);

        // producer w from register-resident Wr2 and batched h
        float w0 = 0.f, w1 = 0.f, w2 = 0.f, w3 = 0.f;
        #pragma unroll
        for (int q = 0; q < 8; ++q) {
            float hq = (j < 4) ? __shfl_sync(0xffffffffu, h0, (j & 3) * 8 + q)
                               : __shfl_sync(0xffffffffu, h1, (j & 3) * 8 + q);
            w0 = fmaf(hq, wr2r[q].x, w0);
            w1 = fmaf(hq, wr2r[q].y, w1);
            w2 = fmaf(hq, wr2r[q].z, w2);
            w3 = fmaf(hq, wr2r[q].w, w3);
        }
        w0 *= wk; w1 *= wk; w2 *= wk; w3 *= wk;

        float wA0 = __shfl_sync(0xffffffffu, w0, srcA);
        float wA1 = __shfl_sync(0xffffffffu, w1, srcA);
        float wA2 = __shfl_sync(0xffffffffu, w2, srcA);
        float wA3 = __shfl_sync(0xffffffffu, w3, srcA);
        float wB0 = __shfl_sync(0xffffffffu, w0, srcB);
        float wB1 = __shfl_sync(0xffffffffu, w1, srcB);
        float wB2 = __shfl_sync(0xffffffffu, w2, srcB);
        float wB3 = __shfl_sync(0xffffffffu, w3, srcB);

        int ee = vj ? (base + j) : (E - 1);
        float4 sh = __ldg((const float4*)ef + ee);           // broadcast

        // 3 address-selected gathers (no divergence, each = one 128B line)
        const float* sup_row = g_sup + (size_t)snd * 32 + cidx;
        const float* vup_row = g_vup + (size_t)snd * 96 + cidx;
        float4 q1 = __ldg((const float4*)(scalA ? sup_row : vup_row));           // se | ve0
        float4 q2 = __ldg((const float4*)(g1 ? vup_row + 32
                                             : (g3 ? vup_row + 64 : sup_row)));  // ve1 | ve2 | se
        float4 q3 = __ldg((const float4*)(g1 ? vup_row + 64 : sup_row));         // ve2 | se

        // dot(ve, sh1) per channel (valid on g1 lanes; selected away elsewhere)
        float d0 = fmaf(q3.x, sh.w, fmaf(q2.x, sh.z, q1.x * sh.y));
        float d1 = fmaf(q3.y, sh.w, fmaf(q2.y, sh.z, q1.y * sh.y));
        float d2 = fmaf(q3.z, sh.w, fmaf(q2.z, sh.z, q1.z * sh.y));
        float d3 = fmaf(q3.w, sh.w, fmaf(q2.w, sh.z, q1.w * sh.y));

        float sA = g1 ? inv_sqrt3 : (g2 ? sh.y : sh.x);
        float sB = g0 ? sh.z : (g2 ? sh.w : sh.x);

        float bA0 = g1 ? d0 : q1.x;
        float bA1 = g1 ? d1 : q1.y;
        float bA2 = g1 ? d2 : q1.z;
        float bA3 = g1 ? d3 : q1.w;

        float bB0 = oddg ? q2.x : q1.x;
        float bB1 = oddg ? q2.y : q1.y;
        float bB2 = oddg ? q2.z : q1.z;
        float bB3 = oddg ? q2.w : q1.w;

        float* dst = g_agg + (size_t)rcv * 256 + loff;
        if (vj) {
            red_add_v4(dst,
                       (wA0 * sA) * bA0, (wA1 * sA) * bA1,
                       (wA2 * sA) * bA2, (wA3 * sA) * bA3);
            red_add_v4(dst + 128,
                       (wB0 * sB) * bB0, (wB1 * sB) * bB1,
                       (wB2 * sB) * bB2, (wB3 * sB) * bB3);
        }
    }
}

// ---------------------------------------------------------------------------
// Kernel C: per-node down-projection + skip average + gated output (UNCHANGED).
// ---------------------------------------------------------------------------
__global__ void node_down_kernel(const float* __restrict__ Wds,  // (64,64)
                                 const float* __restrict__ Wdv,  // (64,32)
                                 float* __restrict__ out,
                                 int N)
{
    int warp = (blockIdx.x * blockDim.x + threadIdx.x) >> 5;
    int lane = threadIdx.x & 31;
    if (warp >= N) return;
    int n = warp;

    const float* ag = g_agg + (size_t)n * 256;
    float a0l  = ag[lane],        a0h  = ag[32 + lane];
    float a1l0 = ag[64 + lane],   a1h0 = ag[96 + lane];
    float a1l1 = ag[128 + lane],  a1h1 = ag[160 + lane];
    float a1l2 = ag[192 + lane],  a1h2 = ag[224 + lane];

    float sc0 = 0.f, sc1 = 0.f, vc0 = 0.f, vc1 = 0.f, vc2 = 0.f;

    #pragma unroll
    for (int c = 0; c < 32; ++c) {
        float b0 = __shfl_sync(0xffffffffu, a0l, c);
        float b1 = __shfl_sync(0xffffffffu, a0h, c);
        sc0 = fmaf(b0, __ldg(Wds + c * 64 + lane), sc0);
        sc0 = fmaf(b1, __ldg(Wds + (32 + c) * 64 + lane), sc0);
        sc1 = fmaf(b0, __ldg(Wds + c * 64 + 32 + lane), sc1);
        sc1 = fmaf(b1, __ldg(Wds + (32 + c) * 64 + 32 + lane), sc1);
        float wv0 = __ldg(Wdv + c * 32 + lane);
        float wv1 = __ldg(Wdv + (32 + c) * 32 + lane);
        vc0 = fmaf(__shfl_sync(0xffffffffu, a1l0, c), wv0, vc0);
        vc0 = fmaf(__shfl_sync(0xffffffffu, a1h0, c), wv1, vc0);
        vc1 = fmaf(__shfl_sync(0xffffffffu, a1l1, c), wv0, vc1);
        vc1 = fmaf(__shfl_sync(0xffffffffu, a1h1, c), wv1, vc1);
        vc2 = fmaf(__shfl_sync(0xffffffffu, a1l2, c), wv0, vc2);
        vc2 = fmaf(__shfl_sync(0xffffffffu, a1h2, c), wv1, vc2);
    }

    const float i2c = 0.125f; // 1/sqrt(64)
    float scl = 0.5f * (sc0 * i2c + g_skip_s[n * 64 + lane]);
    float sch = 0.5f * (sc1 * i2c + g_skip_s[n * 64 + 32 + lane]);
    float feat = silu_f(scl);
    float gate = silu_f(sch);

    float vg0 = 0.5f * (vc0 * i2c + g_skip_v[n * 96 +      lane]) * gate;
    float vg1 = 0.5f * (vc1 * i2c + g_skip_v[n * 96 + 32 + lane]) * gate;
    float vg2 = 0.5f * (vc2 * i2c + g_skip_v[n * 96 + 64 + lane]) * gate;

    float* o = out + (size_t)n * 128;
    o[lane] = feat;
    o[32 + 3 * lane + 0] = vg0;
    o[32 + 3 * lane + 1] = vg1;
    o[32 + 3 * lane + 2] = vg2;
}

// ---------------------------------------------------------------------------
extern "C" void kernel_launch(void* const* d_in, const int* in_sizes, int n_in,
                              void* d_out, int out_size)
{
    const float* nf      = (const float*)d_in[0];
    const float* ef      = (const float*)d_in[1];
    const float* radial  = (const float*)d_in[2];
    const int*   snd     = (const int*)  d_in[3];
    const int*   rcv     = (const int*)  d_in[4];
    const int*   species = (const int*)  d_in[5];
    const float* Wus     = (const float*)d_in[6];
    const float* Wuv     = (const float*)d_in[7];
    const float* Wr1     = (const float*)d_in[8];
    const float* Wr2     = (const float*)d_in[9];
    const float* Wds     = (const float*)d_in[10];
    const float* Wdv     = (const float*)d_in[11];
    const float* Wss     = (const float*)d_in[12];
    const float* Wsv     = (const float*)d_in[13];
    float* out = (float*)d_out;

    int N = in_sizes[0] / 128;
    int E = in_sizes[3];

    int ewarps  = (E + 7) / 8;
    int eblocks = (ewarps + 7) / 8;

    node_up_kernel  <<<(N + 7) / 8, 256>>>(nf, species, Wus, Wuv, Wss, Wsv, N);
    edge_kernel     <<<eblocks, 256>>>(ef, radial, snd, rcv, Wr1, Wr2, E);
    node_down_kernel<<<(N + 7) / 8, 256>>>(Wds, Wdv, out, N);
}

// round 9
// speedup vs baseline: 1.5237x; 1.0552x over previous
#include <cuda_runtime.h>

// Problem constants (fixed by the dataset)
#define MAXN 50000
#define MAXE 800000

// Persistent device scratch (allocation-free rule: __device__ globals)
static __device__ __align__(16) float g_sup[MAXN * 32];     // s_up   [n][c]
static __device__ __align__(16) float g_vup[MAXN * 96];     // v_up   [n][x][c]
static __device__ __align__(16) float g_skip_s[MAXN * 64];  // skip_s [n][d]
static __device__ __align__(16) float g_skip_v[MAXN * 96];  // skip_v [n][x][c]
static __device__ __align__(16) float g_agg[MAXN * 256];    // [n][slot][c]

__device__ __forceinline__ float silu_f(float x) {
    return x / (1.0f + __expf(-x));
}

__device__ __forceinline__ void red_add_v4(float* p, float a, float b, float c, float d) {
    asm volatile("red.global.add.v4.f32 [%0], {%1,%2,%3,%4};"
                 :: "l"(p), "f"(a), "f"(b), "f"(c), "f"(d)
                 : "memory");
}

// Diagnostic no-op: shifts absolute launch index so ncu (which captures
// launch #3) lands on edge_kernel.
__global__ void nop_kernel() {}

// ---------------------------------------------------------------------------
// Kernel A: per-node up-projection + species skip (UNCHANGED, verified).
// ---------------------------------------------------------------------------
__global__ void node_up_kernel(const float* __restrict__ nf,
                               const int*   __restrict__ species,
                               const float* __restrict__ Wus,   // (32,32)
                               const float* __restrict__ Wuv,   // (32,32)
                               const float* __restrict__ Wss,   // (5,32,64)
                               const float* __restrict__ Wsv,   // (5,32,32)
                               int N)
{
    int warp = (blockIdx.x * blockDim.x + threadIdx.x) >> 5;
    int lane = threadIdx.x & 31;
    if (warp >= N) return;
    int n = warp;

    const float* nfp = nf + (size_t)n * 128;
    float s  = nfp[lane];
    float v0 = nfp[32 + lane * 3 + 0];
    float v1 = nfp[32 + lane * 3 + 1];
    float v2 = nfp[32 + lane * 3 + 2];
    int sp = species[n];
    const float* wss = Wss + sp * 2048;
    const float* wsv = Wsv + sp * 1024;

    float sup = 0.f, vu0 = 0.f, vu1 = 0.f, vu2 = 0.f;
    float ss0 = 0.f, ss1 = 0.f, sv0 = 0.f, sv1 = 0.f, sv2 = 0.f;

    #pragma unroll
    for (int c = 0; c < 32; ++c) {
        float sb = __shfl_sync(0xffffffffu, s,  c);
        float b0 = __shfl_sync(0xffffffffu, v0, c);
        float b1 = __shfl_sync(0xffffffffu, v1, c);
        float b2 = __shfl_sync(0xffffffffu, v2, c);
        sup = fmaf(sb, __ldg(Wus + c * 32 + lane), sup);
        float wu = __ldg(Wuv + c * 32 + lane);
        vu0 = fmaf(b0, wu, vu0);
        vu1 = fmaf(b1, wu, vu1);
        vu2 = fmaf(b2, wu, vu2);
        ss0 = fmaf(sb, __ldg(wss + c * 64 + lane), ss0);
        ss1 = fmaf(sb, __ldg(wss + c * 64 + 32 + lane), ss1);
        float wv = __ldg(wsv + c * 32 + lane);
        sv0 = fmaf(b0, wv, sv0);
        sv1 = fmaf(b1, wv, sv1);
        sv2 = fmaf(b2, wv, sv2);
    }

    const float isc = 0.17677669529663687f; // 1/sqrt(32)
    g_sup[n * 32 + lane]             = sup * isc;
    g_vup[n * 96 + 0 * 32 + lane]    = vu0 * isc;
    g_vup[n * 96 + 1 * 32 + lane]    = vu1 * isc;
    g_vup[n * 96 + 2 * 32 + lane]    = vu2 * isc;
    g_skip_s[n * 64 + lane]          = ss0 * isc;
    g_skip_s[n * 64 + 32 + lane]     = ss1 * isc;
    g_skip_v[n * 96 + 0 * 32 + lane] = sv0 * isc;
    g_skip_v[n * 96 + 1 * 32 + lane] = sv1 * isc;
    g_skip_v[n * 96 + 2 * 32 + lane] = sv2 * isc;

    #pragma unroll
    for (int k = 0; k < 2; ++k)
        *(float4*)(g_agg + n * 256 + (k * 32 + lane) * 4) = make_float4(0.f, 0.f, 0.f, 0.f);
}

// ---------------------------------------------------------------------------
// Kernel B: edge kernel (UNCHANGED from round-8 champion).
// ---------------------------------------------------------------------------
__global__ void __launch_bounds__(256, 3) edge_kernel(
    const float* __restrict__ ef,
    const float* __restrict__ radial,
    const int*   __restrict__ snd_,
    const int*   __restrict__ rcv_,
    const float* __restrict__ Wr1,   // (8,8)
    const float* __restrict__ Wr2,   // (8,128)
    int E)
{
    int warp = (blockIdx.x * blockDim.x + threadIdx.x) >> 5;
    int lane = threadIdx.x & 31;
    int base = warp * 8;
    if (base >= E) return;

    const float inv_sqrt8 = 0.35355339059327373f;
    const float inv_sqrt3 = 0.5773502691896258f;
    const float wk        = 0.08838834764831845f; // inv_sqrt8 * 1/sqrt(16)

    int grp  = lane >> 3;
    int srcA = (grp == 0) ? lane : ((grp == 1) ? lane + 16 : lane - 8);
    int srcB = (grp < 2)  ? lane + 8 : srcA;
    int cidx = (lane & 7) * 4;
    int jj   = lane & 7;
    int loff = (lane >> 4) * 64 + (lane & 15) * 4;

    bool g0 = (grp == 0), g1 = (grp == 1), g2 = (grp == 2), g3 = (grp == 3);
    bool scalA = ((grp & 1) == 0);
    bool oddg  = !scalA;

    float wr1r[8];
    #pragma unroll
    for (int i = 0; i < 8; ++i) wr1r[i] = __ldg(Wr1 + i * 8 + jj);
    float4 wr2r[8];
    #pragma unroll
    for (int q = 0; q < 8; ++q) wr2r[q] = __ldg((const float4*)(Wr2 + q * 128 + lane * 4));

    int eic = base + jj; if (eic > E - 1) eic = E - 1;
    int snd8 = __ldg(snd_ + eic);
    int rcv8 = __ldg(rcv_ + eic);

    size_t rbase = (size_t)base * 4 + lane;
    size_t rmax  = (size_t)E * 4 - 1;
    if (rbase > rmax) rbase = rmax;
    float2 rv = __ldg((const float2*)radial + rbase);
    float rvx = rv.x, rvy = rv.y;

    float h0, h1;
    {
        int eb = (lane >> 3) * 4;
        float t0 = 0.f, t1 = 0.f;
        #pragma unroll
        for (int i = 0; i < 8; ++i) {
            int sl = eb + (i >> 1);
            float r0 = (i & 1) ? __shfl_sync(0xffffffffu, rvy, sl)
                               : __shfl_sync(0xffffffffu, rvx, sl);
            float r1 = (i & 1) ? __shfl_sync(0xffffffffu, rvy, sl + 16)
                               : __shfl_sync(0xffffffffu, rvx, sl + 16);
            t0 = fmaf(r0, wr1r[i], t0);
            t1 = fmaf(r1, wr1r[i], t1);
        }
        h0 = silu_f(t0 * inv_sqrt8);
        h1 = silu_f(t1 * inv_sqrt8);
    }

    #pragma unroll
    for (int j = 0; j < 8; ++j) {
        bool vj = (base + j) < E;
        int snd = __shfl_sync(0xffffffffu, snd8, j);
        int rcv = __shfl_sync(0xffffffffu, rcv8, j);

        float w0 = 0.f, w1 = 0.f, w2 = 0.f, w3 = 0.f;
        #pragma unroll
        for (int q = 0; q < 8; ++q) {
            float hq = (j < 4) ? __shfl_sync(0xffffffffu, h0, (j & 3) * 8 + q)
                               : __shfl_sync(0xffffffffu, h1, (j & 3) * 8 + q);
            w0 = fmaf(hq, wr2r[q].x, w0);
            w1 = fmaf(hq, wr2r[q].y, w1);
            w2 = fmaf(hq, wr2r[q].z, w2);
            w3 = fmaf(hq, wr2r[q].w, w3);
        }
        w0 *= wk; w1 *= wk; w2 *= wk; w3 *= wk;

        float wA0 = __shfl_sync(0xffffffffu, w0, srcA);
        float wA1 = __shfl_sync(0xffffffffu, w1, srcA);
        float wA2 = __shfl_sync(0xffffffffu, w2, srcA);
        float wA3 = __shfl_sync(0xffffffffu, w3, srcA);
        float wB0 = __shfl_sync(0xffffffffu, w0, srcB);
        float wB1 = __shfl_sync(0xffffffffu, w1, srcB);
        float wB2 = __shfl_sync(0xffffffffu, w2, srcB);
        float wB3 = __shfl_sync(0xffffffffu, w3, srcB);

        int ee = vj ? (base + j) : (E - 1);
        float4 sh = __ldg((const float4*)ef + ee);           // broadcast

        const float* sup_row = g_sup + (size_t)snd * 32 + cidx;
        const float* vup_row = g_vup + (size_t)snd * 96 + cidx;
        float4 q1 = __ldg((const float4*)(scalA ? sup_row : vup_row));
        float4 q2 = __ldg((const float4*)(g1 ? vup_row + 32
                                             : (g3 ? vup_row + 64 : sup_row)));
        float4 q3 = __ldg((const float4*)(g1 ? vup_row + 64 : sup_row));

        float d0 = fmaf(q3.x, sh.w, fmaf(q2.x, sh.z, q1.x * sh.y));
        float d1 = fmaf(q3.y, sh.w, fmaf(q2.y, sh.z, q1.y * sh.y));
        float d2 = fmaf(q3.z, sh.w, fmaf(q2.z, sh.z, q1.z * sh.y));
        float d3 = fmaf(q3.w, sh.w, fmaf(q2.w, sh.z, q1.w * sh.y));

        float sA = g1 ? inv_sqrt3 : (g2 ? sh.y : sh.x);
        float sB = g0 ? sh.z : (g2 ? sh.w : sh.x);

        float bA0 = g1 ? d0 : q1.x;
        float bA1 = g1 ? d1 : q1.y;
        float bA2 = g1 ? d2 : q1.z;
        float bA3 = g1 ? d3 : q1.w;

        float bB0 = oddg ? q2.x : q1.x;
        float bB1 = oddg ? q2.y : q1.y;
        float bB2 = oddg ? q2.z : q1.z;
        float bB3 = oddg ? q2.w : q1.w;

        float* dst = g_agg + (size_t)rcv * 256 + loff;
        if (vj) {
            red_add_v4(dst,
                       (wA0 * sA) * bA0, (wA1 * sA) * bA1,
                       (wA2 * sA) * bA2, (wA3 * sA) * bA3);
            red_add_v4(dst + 128,
                       (wB0 * sB) * bB0, (wB1 * sB) * bB1,
                       (wB2 * sB) * bB2, (wB3 * sB) * bB3);
        }
    }
}

// ---------------------------------------------------------------------------
// Kernel C: down-projection + skip + gated output, 4 NODES PER WARP.
// Wds/Wdv are node-independent: one weight load now serves 4 nodes
// (192 -> 48 weight LDGs per node). Math identical to verified version.
// ---------------------------------------------------------------------------
__global__ void __launch_bounds__(256) node_down_kernel(
    const float* __restrict__ Wds,  // (64,64)
    const float* __restrict__ Wdv,  // (64,32)
    float* __restrict__ out,
    int N)
{
    int warp = (blockIdx.x * blockDim.x + threadIdx.x) >> 5;
    int lane = threadIdx.x & 31;
    int n0 = warp * 4;
    if (n0 >= N) return;

    float a0l[4], a0h[4], a1l0[4], a1h0[4], a1l1[4], a1h1[4], a1l2[4], a1h2[4];
    #pragma unroll
    for (int k = 0; k < 4; ++k) {
        int n = n0 + k; if (n > N - 1) n = N - 1;
        const float* ag = g_agg + (size_t)n * 256;
        a0l[k]  = ag[lane];        a0h[k]  = ag[32 + lane];
        a1l0[k] = ag[64 + lane];   a1h0[k] = ag[96 + lane];
        a1l1[k] = ag[128 + lane];  a1h1[k] = ag[160 + lane];
        a1l2[k] = ag[192 + lane];  a1h2[k] = ag[224 + lane];
    }

    float sc0[4] = {0.f, 0.f, 0.f, 0.f}, sc1[4] = {0.f, 0.f, 0.f, 0.f};
    float vc0[4] = {0.f, 0.f, 0.f, 0.f}, vc1[4] = {0.f, 0.f, 0.f, 0.f};
    float vc2[4] = {0.f, 0.f, 0.f, 0.f};

    #pragma unroll 4
    for (int c = 0; c < 32; ++c) {
        float wsa  = __ldg(Wds + c * 64 + lane);
        float wsb  = __ldg(Wds + (32 + c) * 64 + lane);
        float wsa2 = __ldg(Wds + c * 64 + 32 + lane);
        float wsb2 = __ldg(Wds + (32 + c) * 64 + 32 + lane);
        float wv0  = __ldg(Wdv + c * 32 + lane);
        float wv1  = __ldg(Wdv + (32 + c) * 32 + lane);
        #pragma unroll
        for (int k = 0; k < 4; ++k) {
            float b0 = __shfl_sync(0xffffffffu, a0l[k], c);
            float b1 = __shfl_sync(0xffffffffu, a0h[k], c);
            sc0[k] = fmaf(b0, wsa,  sc0[k]);
            sc0[k] = fmaf(b1, wsb,  sc0[k]);
            sc1[k] = fmaf(b0, wsa2, sc1[k]);
            sc1[k] = fmaf(b1, wsb2, sc1[k]);
            vc0[k] = fmaf(__shfl_sync(0xffffffffu, a1l0[k], c), wv0, vc0[k]);
            vc0[k] = fmaf(__shfl_sync(0xffffffffu, a1h0[k], c), wv1, vc0[k]);
            vc1[k] = fmaf(__shfl_sync(0xffffffffu, a1l1[k], c), wv0, vc1[k]);
            vc1[k] = fmaf(__shfl_sync(0xffffffffu, a1h1[k], c), wv1, vc1[k]);
            vc2[k] = fmaf(__shfl_sync(0xffffffffu, a1l2[k], c), wv0, vc2[k]);
            vc2[k] = fmaf(__shfl_sync(0xffffffffu, a1h2[k], c), wv1, vc2[k]);
        }
    }

    const float i2c = 0.125f; // 1/sqrt(64)
    #pragma unroll
    for (int k = 0; k < 4; ++k) {
        int n = n0 + k;
        if (n >= N) break;
        float scl = 0.5f * (sc0[k] * i2c + g_skip_s[n * 64 + lane]);
        float sch = 0.5f * (sc1[k] * i2c + g_skip_s[n * 64 + 32 + lane]);
        float feat = silu_f(scl);
        float gate = silu_f(sch);

        float vg0 = 0.5f * (vc0[k] * i2c + g_skip_v[n * 96 +      lane]) * gate;
        float vg1 = 0.5f * (vc1[k] * i2c + g_skip_v[n * 96 + 32 + lane]) * gate;
        float vg2 = 0.5f * (vc2[k] * i2c + g_skip_v[n * 96 + 64 + lane]) * gate;

        float* o = out + (size_t)n * 128;
        o[lane] = feat;
        o[32 + 3 * lane + 0] = vg0;
        o[32 + 3 * lane + 1] = vg1;
        o[32 + 3 * lane + 2] = vg2;
    }
}

// ---------------------------------------------------------------------------
extern "C" void kernel_launch(void* const* d_in, const int* in_sizes, int n_in,
                              void* d_out, int out_size)
{
    const float* nf      = (const float*)d_in[0];
    const float* ef      = (const float*)d_in[1];
    const float* radial  = (const float*)d_in[2];
    const int*   snd     = (const int*)  d_in[3];
    const int*   rcv     = (const int*)  d_in[4];
    const int*   species = (const int*)  d_in[5];
    const float* Wus     = (const float*)d_in[6];
    const float* Wuv     = (const float*)d_in[7];
    const float* Wr1     = (const float*)d_in[8];
    const float* Wr2     = (const float*)d_in[9];
    const float* Wds     = (const float*)d_in[10];
    const float* Wdv     = (const float*)d_in[11];
    const float* Wss     = (const float*)d_in[12];
    const float* Wsv     = (const float*)d_in[13];
    float* out = (float*)d_out;

    int N = in_sizes[0] / 128;
    int E = in_sizes[3];

    int ewarps  = (E + 7) / 8;
    int eblocks = (ewarps + 7) / 8;
    int dwarps  = (N + 3) / 4;
    int dblocks = (dwarps + 7) / 8;

    // Two nops shift absolute launch index so ncu's captured launch (#3)
    // is edge_kernel.
    nop_kernel      <<<1, 32>>>();
    nop_kernel      <<<1, 32>>>();
    node_up_kernel  <<<(N + 7) / 8, 256>>>(nf, species, Wus, Wuv, Wss, Wsv, N);
    edge_kernel     <<<eblocks, 256>>>(ef, radial, snd, rcv, Wr1, Wr2, E);
    node_down_kernel<<<dblocks, 256>>>(Wds, Wdv, out, N);
}